// round 2
// baseline (speedup 1.0000x reference)
#include <cuda_runtime.h>
#include <math.h>
#include <float.h>

// ToolCallingModule — fused implementation.
// Shapes (fixed): B=4,S=4096 -> M=16384 tokens; H=2048, E=256, TH=512, T=128, TOPK=3.
// Output layout (float32): [enhanced 16384*2048][tool_probs 16384*128][should_call 16384]
//
// Algebraic fusions (vs reference):
//   emb_proj[t]  = tool_emb_table[t] @ pg_w1[H:H+E]          (precomputed, 128x512)
//   W_comb       = pg_w2 @ ri_w1[H:2H]                       (precomputed, 512x512)
//   bias_comb    = pg_b2 @ ri_w1[H:2H]                       (precomputed, 512)
//   pass1: [H1 | Xpg | Xri] = X @ [sel_w1 | pg_w1[:H] | ri_w1[:H]]   (one fused read of X)
//   pass4: R1 = relu(Xri + relu(Xpg + emb_proj[tool] + pg_b1) @ W_comb + bias_comb + ri_b1)
//   pass5: enhanced = any_valid ? R1 @ ri_w2 + ri_b2 : X
// gen_params (134MB, [B,S,K,H]) is never materialized; only the selected top-k slot
// is computed (the reference's sequential write loop means last-valid-slot wins).

#define MTOK 16384
#define HD   2048
#define ED   256
#define THD  512
#define TD   128
#define NREG 64

#define OUT_PROBS  (MTOK * HD)
#define OUT_SHOULD (MTOK * HD + MTOK * TD)

// ---------------- scratch (static device globals; no allocation) ----------------
// g_scratchA serves two non-overlapping lifetimes per launch:
//   phase A (precompute): 8 x 512x512 W_comb partials (2 MB used)
//   phase B (pass1+)    : H1 = relu(X @ sel_w1 + b)   (32 MB)
// Both are fully rewritten every launch -> deterministic under graph replay.
__device__ __align__(16) float g_scratchA[MTOK * THD];
__device__ __align__(16) float g_Xpg[MTOK * THD];
__device__ __align__(16) float g_Xri[MTOK * THD];
__device__ __align__(16) float g_R1[MTOK * THD];
__device__ __align__(16) float g_logits[MTOK * TD];
__device__ __align__(16) float g_Wcomb[THD * THD];
__device__ __align__(16) float g_embproj[TD * THD];
__device__ __align__(16) float g_bcP[16 * THD];
__device__ __align__(16) float g_bcomb[THD];
__device__ float g_gatedot[MTOK];
__device__ int   g_tool[MTOK];
__device__ int   g_anyv[MTOK];

// ---------------- generic 128x128x16 SGEMM core (256 threads, 8x8/thread) -------
// TRA: A element is transformed on load: relu(A + embproj[tool[row]][k] + kBias[k])
template <bool TRA>
__device__ __forceinline__ void gemm_core(
    const float* __restrict__ A, int lda,
    const float* __restrict__ B, int ldb,
    int K, int m0, int n0,
    const float* __restrict__ addTab,
    const int*   __restrict__ rowTool,
    const float* __restrict__ kBias,
    float acc[8][8])
{
    __shared__ float As[16][128];
    __shared__ float Bs[16][128];

    const int t  = threadIdx.x;
    const int ty = t >> 4;          // 0..15
    const int tx = t & 15;          // 0..15
    const int ar = t >> 2;          // 0..63   (A load row within tile, +64 for second)
    const int ac = (t & 3) << 2;    // 0,4,8,12 (A load k-offset)
    const int br = t >> 5;          // 0..7    (B load row, +8 for second)
    const int bn = (t & 31) << 2;   // 0..124  (B load col offset)

    int tool0 = 0, tool1 = 0;
    if (TRA) {
        tool0 = rowTool[m0 + ar];
        tool1 = rowTool[m0 + ar + 64];
    }

#pragma unroll
    for (int i = 0; i < 8; i++)
#pragma unroll
        for (int j = 0; j < 8; j++) acc[i][j] = 0.0f;

    const float* Arow0 = A + (size_t)(m0 + ar) * lda;
    const float* Arow1 = A + (size_t)(m0 + ar + 64) * lda;

    for (int k0 = 0; k0 < K; k0 += 16) {
        float4 a0 = *(const float4*)(Arow0 + k0 + ac);
        float4 a1 = *(const float4*)(Arow1 + k0 + ac);
        if (TRA) {
            float4 e0 = *(const float4*)(addTab + tool0 * THD + k0 + ac);
            float4 e1 = *(const float4*)(addTab + tool1 * THD + k0 + ac);
            float4 bb = *(const float4*)(kBias + k0 + ac);
            a0.x = fmaxf(a0.x + e0.x + bb.x, 0.0f);
            a0.y = fmaxf(a0.y + e0.y + bb.y, 0.0f);
            a0.z = fmaxf(a0.z + e0.z + bb.z, 0.0f);
            a0.w = fmaxf(a0.w + e0.w + bb.w, 0.0f);
            a1.x = fmaxf(a1.x + e1.x + bb.x, 0.0f);
            a1.y = fmaxf(a1.y + e1.y + bb.y, 0.0f);
            a1.z = fmaxf(a1.z + e1.z + bb.z, 0.0f);
            a1.w = fmaxf(a1.w + e1.w + bb.w, 0.0f);
        }
        float4 b0 = *(const float4*)(B + (size_t)(k0 + br) * ldb + n0 + bn);
        float4 b1 = *(const float4*)(B + (size_t)(k0 + br + 8) * ldb + n0 + bn);

        __syncthreads();
        As[ac + 0][ar] = a0.x; As[ac + 1][ar] = a0.y;
        As[ac + 2][ar] = a0.z; As[ac + 3][ar] = a0.w;
        As[ac + 0][ar + 64] = a1.x; As[ac + 1][ar + 64] = a1.y;
        As[ac + 2][ar + 64] = a1.z; As[ac + 3][ar + 64] = a1.w;
        *(float4*)&Bs[br][bn]     = b0;
        *(float4*)&Bs[br + 8][bn] = b1;
        __syncthreads();

#pragma unroll
        for (int kk = 0; kk < 16; kk++) {
            float4 fa0 = *(const float4*)&As[kk][ty * 8];
            float4 fa1 = *(const float4*)&As[kk][ty * 8 + 4];
            float4 fb0 = *(const float4*)&Bs[kk][tx * 8];
            float4 fb1 = *(const float4*)&Bs[kk][tx * 8 + 4];
            float av[8] = {fa0.x, fa0.y, fa0.z, fa0.w, fa1.x, fa1.y, fa1.z, fa1.w};
            float bv[8] = {fb0.x, fb0.y, fb0.z, fb0.w, fb1.x, fb1.y, fb1.z, fb1.w};
#pragma unroll
            for (int i = 0; i < 8; i++)
#pragma unroll
                for (int j = 0; j < 8; j++)
                    acc[i][j] = fmaf(av[i], bv[j], acc[i][j]);
        }
    }
}

// ---------------- precompute kernels ----------------

// W_comb partials into g_scratchA (phase-A alias):
//   partial[z] = pg_w2[:, z*256:(z+1)*256] @ ri_w1[H+z*256 : H+(z+1)*256, :]
__global__ __launch_bounds__(256) void k_wcombp(const float* __restrict__ pw2,
                                                const float* __restrict__ rw1) {
    int z = blockIdx.z;
    float acc[8][8];
    gemm_core<false>(pw2 + z * 256, HD,
                     rw1 + (size_t)(HD + z * 256) * THD, THD,
                     256, blockIdx.x * 128, blockIdx.y * 128,
                     nullptr, nullptr, nullptr, acc);
    int ty = threadIdx.x >> 4, tx = threadIdx.x & 15;
    float* dst = g_scratchA + (size_t)z * THD * THD;
#pragma unroll
    for (int i = 0; i < 8; i++) {
        int m = blockIdx.x * 128 + ty * 8 + i;
#pragma unroll
        for (int j = 0; j < 8; j++)
            dst[m * THD + blockIdx.y * 128 + tx * 8 + j] = acc[i][j];
    }
}

__global__ void k_wcomb_red() {
    int idx = blockIdx.x * blockDim.x + threadIdx.x;
    if (idx >= THD * THD) return;
    float s = 0.0f;
#pragma unroll
    for (int z = 0; z < 8; z++) s += g_scratchA[(size_t)z * THD * THD + idx];
    g_Wcomb[idx] = s;
}

// emb_proj[t][j] = sum_e table[t][e] * pg_w1[H+e][j]
__global__ __launch_bounds__(512) void k_embproj(const float* __restrict__ tab,
                                                 const float* __restrict__ pw1) {
    __shared__ float st[ED];
    int t = blockIdx.x;
    if (threadIdx.x < ED) st[threadIdx.x] = tab[t * ED + threadIdx.x];
    __syncthreads();
    int j = threadIdx.x;  // 0..511
    float acc = 0.0f;
    for (int e = 0; e < ED; e++)
        acc = fmaf(st[e], __ldg(pw1 + (size_t)(HD + e) * THD + j), acc);
    g_embproj[t * THD + j] = acc;
}

// bias_comb partials: sum_k pg_b2[k] * ri_w1[H+k][j]
__global__ __launch_bounds__(512) void k_bcombp(const float* __restrict__ pb2,
                                                const float* __restrict__ rw1) {
    int z = blockIdx.x;  // 16 chunks of 128
    int j = threadIdx.x;
    float acc = 0.0f;
    for (int k = z * 128; k < z * 128 + 128; k++)
        acc = fmaf(__ldg(pb2 + k), __ldg(rw1 + (size_t)(HD + k) * THD + j), acc);
    g_bcP[z * THD + j] = acc;
}

__global__ void k_bcomb_red() {
    int j = blockIdx.x * blockDim.x + threadIdx.x;
    if (j >= THD) return;
    float s = 0.0f;
#pragma unroll
    for (int z = 0; z < 16; z++) s += g_bcP[z * THD + j];
    g_bcomb[j] = s;
}

// gate dot: one warp per token.  sigmoid(x) > 0.5  <=>  x > 0
__global__ __launch_bounds__(256) void k_gatedot(const float* __restrict__ X,
                                                 const float* __restrict__ gw,
                                                 const float* __restrict__ gb) {
    int warp = (blockIdx.x * blockDim.x + threadIdx.x) >> 5;
    int lane = threadIdx.x & 31;
    if (warp >= MTOK) return;
    const float* x = X + (size_t)warp * HD;
    float s = 0.0f;
    for (int k = lane; k < HD; k += 32) s = fmaf(x[k], __ldg(gw + k), s);
#pragma unroll
    for (int off = 16; off; off >>= 1) s += __shfl_xor_sync(0xFFFFFFFFu, s, off);
    if (lane == 0) g_gatedot[warp] = s + gb[0];
}

// ---------------- main passes ----------------

// pass1: fused [H1|Xpg|Xri] = X @ [sel_w1 | pg_w1[:H] | ri_w1[:H]]  (X read once per tile-col)
__global__ __launch_bounds__(256) void k_pass1(const float* __restrict__ X,
                                               const float* __restrict__ sw1,
                                               const float* __restrict__ sb1,
                                               const float* __restrict__ pw1,
                                               const float* __restrict__ rw1) {
    int m0  = blockIdx.x * 128;
    int grp = blockIdx.y >> 2;          // 0=sel, 1=pg, 2=ri
    int nc0 = (blockIdx.y & 3) * 128;   // column offset within 512
    const float* B = (grp == 0) ? sw1 : (grp == 1 ? pw1 : rw1);
    float acc[8][8];
    gemm_core<false>(X, HD, B, THD, HD, m0, nc0, nullptr, nullptr, nullptr, acc);
    int ty = threadIdx.x >> 4, tx = threadIdx.x & 15;
    if (grp == 0) {
#pragma unroll
        for (int i = 0; i < 8; i++) {
            int m = m0 + ty * 8 + i;
#pragma unroll
            for (int j = 0; j < 8; j++) {
                int n = nc0 + tx * 8 + j;
                g_scratchA[m * THD + n] = fmaxf(acc[i][j] + sb1[n], 0.0f);  // H1
            }
        }
    } else {
        float* dst = (grp == 1) ? g_Xpg : g_Xri;
#pragma unroll
        for (int i = 0; i < 8; i++) {
            int m = m0 + ty * 8 + i;
#pragma unroll
            for (int j = 0; j < 8; j++)
                dst[m * THD + nc0 + tx * 8 + j] = acc[i][j];
        }
    }
}

// pass2: logits = H1 @ sel_w2 + sel_b2
__global__ __launch_bounds__(256) void k_pass2(const float* __restrict__ sw2,
                                               const float* __restrict__ sb2) {
    int m0 = blockIdx.x * 128;
    float acc[8][8];
    gemm_core<false>(g_scratchA, THD, sw2, TD, THD, m0, 0, nullptr, nullptr, nullptr, acc);
    int ty = threadIdx.x >> 4, tx = threadIdx.x & 15;
#pragma unroll
    for (int i = 0; i < 8; i++) {
        int m = m0 + ty * 8 + i;
#pragma unroll
        for (int j = 0; j < 8; j++) {
            int n = tx * 8 + j;
            g_logits[m * TD + n] = acc[i][j] + sb2[n];
        }
    }
}

// post: softmax + top-3 + gate/validity; one warp per token
__global__ __launch_bounds__(256) void k_post(float* __restrict__ out) {
    int warp = (blockIdx.x * blockDim.x + threadIdx.x) >> 5;
    int lane = threadIdx.x & 31;
    if (warp >= MTOK) return;
    const float* l = g_logits + warp * TD;

    float v[4];
#pragma unroll
    for (int i = 0; i < 4; i++) v[i] = l[lane + 32 * i];

    float mx = fmaxf(fmaxf(v[0], v[1]), fmaxf(v[2], v[3]));
#pragma unroll
    for (int off = 16; off; off >>= 1) mx = fmaxf(mx, __shfl_xor_sync(0xFFFFFFFFu, mx, off));

    float e[4], s = 0.0f;
#pragma unroll
    for (int i = 0; i < 4; i++) { e[i] = expf(v[i] - mx); s += e[i]; }
#pragma unroll
    for (int off = 16; off; off >>= 1) s += __shfl_xor_sync(0xFFFFFFFFu, s, off);
    float inv = 1.0f / s;
#pragma unroll
    for (int i = 0; i < 4; i++)
        out[OUT_PROBS + warp * TD + lane + 32 * i] = e[i] * inv;

    // top-3 (ties -> lowest index, matching jax.lax.top_k)
    int chosen[3];
    unsigned excl = 0;
#pragma unroll
    for (int p = 0; p < 3; p++) {
        float bv = -FLT_MAX;
        int bi = 1 << 30;
#pragma unroll
        for (int i = 0; i < 4; i++) {
            if (!((excl >> i) & 1u)) {
                int idx = lane + 32 * i;
                if (v[i] > bv) { bv = v[i]; bi = idx; }
            }
        }
#pragma unroll
        for (int off = 16; off; off >>= 1) {
            float ov = __shfl_xor_sync(0xFFFFFFFFu, bv, off);
            int   oi = __shfl_xor_sync(0xFFFFFFFFu, bi, off);
            if (ov > bv || (ov == bv && oi < bi)) { bv = ov; bi = oi; }
        }
        chosen[p] = bi;
        if ((bi & 31) == lane) excl |= 1u << (bi >> 5);
    }

    bool should = g_gatedot[warp] > 0.0f;
    int last = -1;
#pragma unroll
    for (int k = 0; k < 3; k++)
        if (chosen[k] < NREG && should) last = k;
    int selk = last < 0 ? 0 : last;

    if (lane == 0) {
        g_tool[warp] = chosen[selk];
        g_anyv[warp] = (last >= 0) ? 1 : 0;
        out[OUT_SHOULD + warp] = should ? 1.0f : 0.0f;
    }
}

// pass4: R1 = relu(Xri + relu(Xpg + embproj[tool] + pg_b1) @ Wcomb + bcomb + ri_b1)
__global__ __launch_bounds__(256) void k_pass4(const float* __restrict__ pb1,
                                               const float* __restrict__ rb1) {
    int m0 = blockIdx.x * 128;
    int n0 = blockIdx.y * 128;
    float acc[8][8];
    gemm_core<true>(g_Xpg, THD, g_Wcomb, THD, THD, m0, n0,
                    g_embproj, g_tool, pb1, acc);
    int ty = threadIdx.x >> 4, tx = threadIdx.x & 15;
    // per-column epilogue constants for this thread's 8 columns
    float cadd[8];
#pragma unroll
    for (int j = 0; j < 8; j++) {
        int n = n0 + tx * 8 + j;
        cadd[j] = g_bcomb[n] + rb1[n];
    }
#pragma unroll
    for (int i = 0; i < 8; i++) {
        int m = m0 + ty * 8 + i;
#pragma unroll
        for (int j = 0; j < 8; j++) {
            int n = n0 + tx * 8 + j;
            float r = acc[i][j] + g_Xri[m * THD + n] + cadd[j];
            g_R1[m * THD + n] = fmaxf(r, 0.0f);
        }
    }
}

// pass5: enhanced = anyv ? R1 @ ri_w2 + ri_b2 : X
__global__ __launch_bounds__(256) void k_pass5(const float* __restrict__ X,
                                               const float* __restrict__ rw2,
                                               const float* __restrict__ rb2,
                                               float* __restrict__ out) {
    int m0 = blockIdx.x * 128;
    int n0 = blockIdx.y * 128;
    float acc[8][8];
    gemm_core<false>(g_R1, THD, rw2, HD, THD, m0, n0, nullptr, nullptr, nullptr, acc);
    int ty = threadIdx.x >> 4, tx = threadIdx.x & 15;
#pragma unroll
    for (int i = 0; i < 8; i++) {
        int m = m0 + ty * 8 + i;
        int av = g_anyv[m];
#pragma unroll
        for (int j = 0; j < 8; j++) {
            int n = n0 + tx * 8 + j;
            float c = acc[i][j] + rb2[n];
            out[(size_t)m * HD + n] = av ? c : X[(size_t)m * HD + n];
        }
    }
}

// ---------------- launch ----------------
extern "C" void kernel_launch(void* const* d_in, const int* in_sizes, int n_in,
                              void* d_out, int out_size) {
    (void)in_sizes; (void)n_in; (void)out_size;
    const float* X   = (const float*)d_in[0];
    const float* tab = (const float*)d_in[1];
    const float* gw  = (const float*)d_in[2];
    const float* gb  = (const float*)d_in[3];
    const float* sw1 = (const float*)d_in[4];
    const float* sb1 = (const float*)d_in[5];
    const float* sw2 = (const float*)d_in[6];
    const float* sb2 = (const float*)d_in[7];
    const float* pw1 = (const float*)d_in[8];
    const float* pb1 = (const float*)d_in[9];
    const float* pw2 = (const float*)d_in[10];
    const float* pb2 = (const float*)d_in[11];
    const float* rw1 = (const float*)d_in[12];
    const float* rb1 = (const float*)d_in[13];
    const float* rw2 = (const float*)d_in[14];
    const float* rb2 = (const float*)d_in[15];
    float* out = (float*)d_out;

    // phase A: precompute (g_scratchA holds W_comb partials)
    k_wcombp<<<dim3(4, 4, 8), 256>>>(pw2, rw1);
    k_wcomb_red<<<(THD * THD + 255) / 256, 256>>>();
    k_embproj<<<TD, 512>>>(tab, pw1);
    k_bcombp<<<16, 512>>>(pb2, rw1);
    k_bcomb_red<<<2, 256>>>();
    k_gatedot<<<2048, 256>>>(X, gw, gb);
    // phase B: token passes (g_scratchA becomes H1)
    k_pass1<<<dim3(128, 12), 256>>>(X, sw1, sb1, pw1, rw1);
    k_pass2<<<dim3(128, 1), 256>>>(sw2, sb2);
    k_post<<<2048, 256>>>(out);
    k_pass4<<<dim3(128, 4), 256>>>(pb1, rb1);
    k_pass5<<<dim3(128, 16), 256>>>(X, rw2, rb2, out);
}

// round 4
// speedup vs baseline: 1.6259x; 1.6259x over previous
#include <cuda_runtime.h>
#include <math.h>
#include <float.h>

// ToolCallingModule — fused + validity-compacted implementation.
// Shapes (fixed): B=4,S=4096 -> M=16384 tokens; H=2048, E=256, TH=512, T=128, TOPK=3.
// Output layout (float32): [enhanced 16384*2048][tool_probs 16384*128][should_call 16384]
//
// Algebraic fusions (vs reference):
//   emb_proj[t]  = tool_emb_table[t] @ pg_w1[H:H+E]          (precomputed, 128x512)
//   W_comb       = pg_w2 @ ri_w1[H:2H]                       (precomputed, 512x512)
//   bias_comb    = pg_b2 @ ri_w1[H:2H]                       (precomputed, 512)
//   selector:  H1 = relu(X @ sel_w1 + b); logits = H1 @ sel_w2 + b   (ALL tokens)
//   compaction: only tokens with any_valid (~44%) proceed; others copy X to out.
//   pass1b (compact, gathered): [Xpg | Xri] = X[vidx] @ [pg_w1[:H] | ri_w1[:H]]
//   pass4  (compact): R1 = relu(Xri + relu(Xpg + emb_proj[tool] + pg_b1) @ W_comb + bias_comb + ri_b1)
//   pass5  (compact, scattered): out[vidx] = R1 @ ri_w2 + ri_b2
// gen_params (134MB) never materialized; only the selected top-k slot is computed.
// Compaction order via atomicAdd is nondeterministic, but every output element is
// a pure function of its token id -> outputs identical across graph replays.

#define MTOK 16384
#define HD   2048
#define ED   256
#define THD  512
#define TD   128
#define NREG 64

#define OUT_PROBS  (MTOK * HD)
#define OUT_SHOULD (MTOK * HD + MTOK * TD)

// ---------------- scratch (static device globals; no allocation) ----------------
// g_scratchA lifetimes per launch: (A) W_comb partials, (B) H1. Fully rewritten
// each launch -> deterministic under graph replay.
__device__ __align__(16) float g_scratchA[MTOK * THD];
__device__ __align__(16) float g_Xpg[MTOK * THD];   // compact rows [cnt, 512]
__device__ __align__(16) float g_Xri[MTOK * THD];   // compact rows [cnt, 512]
__device__ __align__(16) float g_R1[MTOK * THD];    // compact rows [cnt, 512]
__device__ __align__(16) float g_logits[MTOK * TD];
__device__ __align__(16) float g_Wcomb[THD * THD];
__device__ __align__(16) float g_embproj[TD * THD];
__device__ __align__(16) float g_bcP[16 * THD];
__device__ __align__(16) float g_bcomb[THD];
__device__ float g_gatedot[MTOK];
__device__ int   g_anyv[MTOK];
__device__ int   g_vidx[MTOK];   // compact -> token
__device__ int   g_ctool[MTOK];  // compact -> selected tool id
__device__ int   g_cnt;

// ---------------- generic 128x128x16 SGEMM core (256 threads, 8x8/thread) -------
// GATHER: A rows come from vidx[] (guarded by cnt)
// TRA   : A element transformed on load: relu(A + addTab[rowTool[m]][k] + kBias[k])
template <bool TRA, bool GATHER>
__device__ __forceinline__ void gemm_core(
    const float* __restrict__ A, int lda,
    const float* __restrict__ B, int ldb,
    int K, int m0, int n0,
    const float* __restrict__ addTab,
    const int*   __restrict__ rowTool,
    const float* __restrict__ kBias,
    const int*   __restrict__ vidx, int cnt,
    float acc[8][8])
{
    __shared__ float As[16][128];
    __shared__ float Bs[16][128];

    const int t  = threadIdx.x;
    const int ty = t >> 4;          // 0..15
    const int tx = t & 15;          // 0..15
    const int ar = t >> 2;          // 0..63   (A load row within tile, +64 for second)
    const int ac = (t & 3) << 2;    // 0,4,8,12 (A load k-offset)
    const int br = t >> 5;          // 0..7    (B load row, +8 for second)
    const int bn = (t & 31) << 2;   // 0..124  (B load col offset)

    int row0 = m0 + ar, row1 = m0 + ar + 64;
    if (GATHER) {
        row0 = (row0 < cnt) ? vidx[row0] : 0;
        row1 = (row1 < cnt) ? vidx[row1] : 0;
    }
    int tool0 = 0, tool1 = 0;
    if (TRA) {
        tool0 = (m0 + ar      < cnt) ? rowTool[m0 + ar]      : 0;
        tool1 = (m0 + ar + 64 < cnt) ? rowTool[m0 + ar + 64] : 0;
    }

#pragma unroll
    for (int i = 0; i < 8; i++)
#pragma unroll
        for (int j = 0; j < 8; j++) acc[i][j] = 0.0f;

    const float* Arow0 = A + (size_t)row0 * lda;
    const float* Arow1 = A + (size_t)row1 * lda;

    for (int k0 = 0; k0 < K; k0 += 16) {
        float4 a0 = *(const float4*)(Arow0 + k0 + ac);
        float4 a1 = *(const float4*)(Arow1 + k0 + ac);
        if (TRA) {
            float4 e0 = *(const float4*)(addTab + tool0 * THD + k0 + ac);
            float4 e1 = *(const float4*)(addTab + tool1 * THD + k0 + ac);
            float4 bb = *(const float4*)(kBias + k0 + ac);
            a0.x = fmaxf(a0.x + e0.x + bb.x, 0.0f);
            a0.y = fmaxf(a0.y + e0.y + bb.y, 0.0f);
            a0.z = fmaxf(a0.z + e0.z + bb.z, 0.0f);
            a0.w = fmaxf(a0.w + e0.w + bb.w, 0.0f);
            a1.x = fmaxf(a1.x + e1.x + bb.x, 0.0f);
            a1.y = fmaxf(a1.y + e1.y + bb.y, 0.0f);
            a1.z = fmaxf(a1.z + e1.z + bb.z, 0.0f);
            a1.w = fmaxf(a1.w + e1.w + bb.w, 0.0f);
        }
        float4 b0 = *(const float4*)(B + (size_t)(k0 + br) * ldb + n0 + bn);
        float4 b1 = *(const float4*)(B + (size_t)(k0 + br + 8) * ldb + n0 + bn);

        __syncthreads();
        As[ac + 0][ar] = a0.x; As[ac + 1][ar] = a0.y;
        As[ac + 2][ar] = a0.z; As[ac + 3][ar] = a0.w;
        As[ac + 0][ar + 64] = a1.x; As[ac + 1][ar + 64] = a1.y;
        As[ac + 2][ar + 64] = a1.z; As[ac + 3][ar + 64] = a1.w;
        *(float4*)&Bs[br][bn]     = b0;
        *(float4*)&Bs[br + 8][bn] = b1;
        __syncthreads();

#pragma unroll
        for (int kk = 0; kk < 16; kk++) {
            float4 fa0 = *(const float4*)&As[kk][ty * 8];
            float4 fa1 = *(const float4*)&As[kk][ty * 8 + 4];
            float4 fb0 = *(const float4*)&Bs[kk][tx * 8];
            float4 fb1 = *(const float4*)&Bs[kk][tx * 8 + 4];
            float av[8] = {fa0.x, fa0.y, fa0.z, fa0.w, fa1.x, fa1.y, fa1.z, fa1.w};
            float bv[8] = {fb0.x, fb0.y, fb0.z, fb0.w, fb1.x, fb1.y, fb1.z, fb1.w};
#pragma unroll
            for (int i = 0; i < 8; i++)
#pragma unroll
                for (int j = 0; j < 8; j++)
                    acc[i][j] = fmaf(av[i], bv[j], acc[i][j]);
        }
    }
}

// ---------------- precompute kernels ----------------

__global__ __launch_bounds__(256) void k_wcombp(const float* __restrict__ pw2,
                                                const float* __restrict__ rw1) {
    int z = blockIdx.z;
    float acc[8][8];
    gemm_core<false, false>(pw2 + z * 256, HD,
                            rw1 + (size_t)(HD + z * 256) * THD, THD,
                            256, blockIdx.x * 128, blockIdx.y * 128,
                            nullptr, nullptr, nullptr, nullptr, 0, acc);
    int ty = threadIdx.x >> 4, tx = threadIdx.x & 15;
    float* dst = g_scratchA + (size_t)z * THD * THD;
#pragma unroll
    for (int i = 0; i < 8; i++) {
        int m = blockIdx.x * 128 + ty * 8 + i;
#pragma unroll
        for (int j = 0; j < 8; j++)
            dst[m * THD + blockIdx.y * 128 + tx * 8 + j] = acc[i][j];
    }
}

__global__ void k_wcomb_red() {
    int idx = blockIdx.x * blockDim.x + threadIdx.x;
    if (idx >= THD * THD) return;
    float s = 0.0f;
#pragma unroll
    for (int z = 0; z < 8; z++) s += g_scratchA[(size_t)z * THD * THD + idx];
    g_Wcomb[idx] = s;
}

__global__ __launch_bounds__(512) void k_embproj(const float* __restrict__ tab,
                                                 const float* __restrict__ pw1) {
    __shared__ float st[ED];
    int t = blockIdx.x;
    if (threadIdx.x < ED) st[threadIdx.x] = tab[t * ED + threadIdx.x];
    __syncthreads();
    int j = threadIdx.x;  // 0..511
    float acc = 0.0f;
    for (int e = 0; e < ED; e++)
        acc = fmaf(st[e], __ldg(pw1 + (size_t)(HD + e) * THD + j), acc);
    g_embproj[t * THD + j] = acc;
}

__global__ __launch_bounds__(512) void k_bcombp(const float* __restrict__ pb2,
                                                const float* __restrict__ rw1) {
    int z = blockIdx.x;
    int j = threadIdx.x;
    float acc = 0.0f;
    for (int k = z * 128; k < z * 128 + 128; k++)
        acc = fmaf(__ldg(pb2 + k), __ldg(rw1 + (size_t)(HD + k) * THD + j), acc);
    g_bcP[z * THD + j] = acc;
}

__global__ void k_bcomb_red() {
    int j = blockIdx.x * blockDim.x + threadIdx.x;
    if (j >= THD) return;
    float s = 0.0f;
#pragma unroll
    for (int z = 0; z < 16; z++) s += g_bcP[z * THD + j];
    g_bcomb[j] = s;
}

// gate dot: one warp per token.  sigmoid(x) > 0.5  <=>  x > 0.
// Also resets the compaction counter (runs strictly before k_post in-stream).
__global__ __launch_bounds__(256) void k_gatedot(const float* __restrict__ X,
                                                 const float* __restrict__ gw,
                                                 const float* __restrict__ gb) {
    if (blockIdx.x == 0 && threadIdx.x == 0) g_cnt = 0;
    int warp = (blockIdx.x * blockDim.x + threadIdx.x) >> 5;
    int lane = threadIdx.x & 31;
    if (warp >= MTOK) return;
    const float* x = X + (size_t)warp * HD;
    float s = 0.0f;
    for (int k = lane; k < HD; k += 32) s = fmaf(x[k], __ldg(gw + k), s);
#pragma unroll
    for (int off = 16; off; off >>= 1) s += __shfl_xor_sync(0xFFFFFFFFu, s, off);
    if (lane == 0) g_gatedot[warp] = s + gb[0];
}

// ---------------- selector path (all tokens) ----------------

// H1 = relu(X @ sel_w1 + sel_b1)
__global__ __launch_bounds__(256) void k_pass1sel(const float* __restrict__ X,
                                                  const float* __restrict__ sw1,
                                                  const float* __restrict__ sb1) {
    int m0  = blockIdx.x * 128;
    int nc0 = blockIdx.y * 128;
    float acc[8][8];
    gemm_core<false, false>(X, HD, sw1, THD, HD, m0, nc0,
                            nullptr, nullptr, nullptr, nullptr, 0, acc);
    int ty = threadIdx.x >> 4, tx = threadIdx.x & 15;
#pragma unroll
    for (int i = 0; i < 8; i++) {
        int m = m0 + ty * 8 + i;
#pragma unroll
        for (int j = 0; j < 8; j++) {
            int n = nc0 + tx * 8 + j;
            g_scratchA[m * THD + n] = fmaxf(acc[i][j] + sb1[n], 0.0f);  // H1
        }
    }
}

// logits = H1 @ sel_w2 + sel_b2
__global__ __launch_bounds__(256) void k_pass2(const float* __restrict__ sw2,
                                               const float* __restrict__ sb2) {
    int m0 = blockIdx.x * 128;
    float acc[8][8];
    gemm_core<false, false>(g_scratchA, THD, sw2, TD, THD, m0, 0,
                            nullptr, nullptr, nullptr, nullptr, 0, acc);
    int ty = threadIdx.x >> 4, tx = threadIdx.x & 15;
#pragma unroll
    for (int i = 0; i < 8; i++) {
        int m = m0 + ty * 8 + i;
#pragma unroll
        for (int j = 0; j < 8; j++) {
            int n = tx * 8 + j;
            g_logits[m * TD + n] = acc[i][j] + sb2[n];
        }
    }
}

// post: softmax + top-3 + gate/validity + compaction list; one warp per token
__global__ __launch_bounds__(256) void k_post(float* __restrict__ out) {
    int warp = (blockIdx.x * blockDim.x + threadIdx.x) >> 5;
    int lane = threadIdx.x & 31;
    if (warp >= MTOK) return;
    const float* l = g_logits + warp * TD;

    float v[4];
#pragma unroll
    for (int i = 0; i < 4; i++) v[i] = l[lane + 32 * i];

    float mx = fmaxf(fmaxf(v[0], v[1]), fmaxf(v[2], v[3]));
#pragma unroll
    for (int off = 16; off; off >>= 1) mx = fmaxf(mx, __shfl_xor_sync(0xFFFFFFFFu, mx, off));

    float e[4], s = 0.0f;
#pragma unroll
    for (int i = 0; i < 4; i++) { e[i] = expf(v[i] - mx); s += e[i]; }
#pragma unroll
    for (int off = 16; off; off >>= 1) s += __shfl_xor_sync(0xFFFFFFFFu, s, off);
    float inv = 1.0f / s;
#pragma unroll
    for (int i = 0; i < 4; i++)
        out[OUT_PROBS + warp * TD + lane + 32 * i] = e[i] * inv;

    // top-3 (ties -> lowest index, matching jax.lax.top_k)
    int chosen[3];
    unsigned excl = 0;
#pragma unroll
    for (int p = 0; p < 3; p++) {
        float bv = -FLT_MAX;
        int bi = 1 << 30;
#pragma unroll
        for (int i = 0; i < 4; i++) {
            if (!((excl >> i) & 1u)) {
                int idx = lane + 32 * i;
                if (v[i] > bv) { bv = v[i]; bi = idx; }
            }
        }
#pragma unroll
        for (int off = 16; off; off >>= 1) {
            float ov = __shfl_xor_sync(0xFFFFFFFFu, bv, off);
            int   oi = __shfl_xor_sync(0xFFFFFFFFu, bi, off);
            if (ov > bv || (ov == bv && oi < bi)) { bv = ov; bi = oi; }
        }
        chosen[p] = bi;
        if ((bi & 31) == lane) excl |= 1u << (bi >> 5);
    }

    bool should = g_gatedot[warp] > 0.0f;
    int last = -1;
#pragma unroll
    for (int k = 0; k < 3; k++)
        if (chosen[k] < NREG && should) last = k;
    int selk = last < 0 ? 0 : last;

    if (lane == 0) {
        int anyv = (last >= 0) ? 1 : 0;
        g_anyv[warp] = anyv;
        out[OUT_SHOULD + warp] = should ? 1.0f : 0.0f;
        if (anyv) {
            int pos = atomicAdd(&g_cnt, 1);
            g_vidx[pos]  = warp;
            g_ctool[pos] = chosen[selk];
        }
    }
}

// invalid tokens: out row = X row (bandwidth-only). 512 threads = one row of float4s.
__global__ __launch_bounds__(512) void k_copyinv(const float* __restrict__ X,
                                                 float* __restrict__ out) {
    int token = blockIdx.x;
    if (g_anyv[token]) return;
    const float4* src = (const float4*)(X + (size_t)token * HD);
    float4* dst = (float4*)(out + (size_t)token * HD);
    dst[threadIdx.x] = src[threadIdx.x];
}

// ---------------- compacted value path ----------------

// [Xpg | Xri](compact) = X[vidx] @ [pg_w1[:H] | ri_w1[:H]]
__global__ __launch_bounds__(256) void k_pass1b(const float* __restrict__ X,
                                                const float* __restrict__ pw1,
                                                const float* __restrict__ rw1) {
    int cnt = g_cnt;
    int m0 = blockIdx.x * 128;
    if (m0 >= cnt) return;
    int grp = blockIdx.y >> 2;          // 0=pg, 1=ri
    int nc0 = (blockIdx.y & 3) * 128;
    const float* B = grp ? rw1 : pw1;
    float acc[8][8];
    gemm_core<false, true>(X, HD, B, THD, HD, m0, nc0,
                           nullptr, nullptr, nullptr, g_vidx, cnt, acc);
    float* dst = grp ? g_Xri : g_Xpg;
    int ty = threadIdx.x >> 4, tx = threadIdx.x & 15;
#pragma unroll
    for (int i = 0; i < 8; i++) {
        int m = m0 + ty * 8 + i;
        if (m >= cnt) break;
#pragma unroll
        for (int j = 0; j < 8; j++)
            dst[m * THD + nc0 + tx * 8 + j] = acc[i][j];
    }
}

// R1 = relu(Xri + relu(Xpg + embproj[tool] + pg_b1) @ Wcomb + bcomb + ri_b1)  (compact)
__global__ __launch_bounds__(256) void k_pass4(const float* __restrict__ pb1,
                                               const float* __restrict__ rb1) {
    int cnt = g_cnt;
    int m0 = blockIdx.x * 128;
    if (m0 >= cnt) return;
    int n0 = blockIdx.y * 128;
    float acc[8][8];
    gemm_core<true, false>(g_Xpg, THD, g_Wcomb, THD, THD, m0, n0,
                           g_embproj, g_ctool, pb1, nullptr, cnt, acc);
    int ty = threadIdx.x >> 4, tx = threadIdx.x & 15;
    float cadd[8];
#pragma unroll
    for (int j = 0; j < 8; j++) {
        int n = n0 + tx * 8 + j;
        cadd[j] = g_bcomb[n] + rb1[n];
    }
#pragma unroll
    for (int i = 0; i < 8; i++) {
        int m = m0 + ty * 8 + i;
        if (m >= cnt) break;
#pragma unroll
        for (int j = 0; j < 8; j++) {
            int n = n0 + tx * 8 + j;
            float r = acc[i][j] + g_Xri[m * THD + n] + cadd[j];
            g_R1[m * THD + n] = fmaxf(r, 0.0f);
        }
    }
}

// out[vidx] = R1 @ ri_w2 + ri_b2  (compact, scattered)
__global__ __launch_bounds__(256) void k_pass5(const float* __restrict__ rw2,
                                               const float* __restrict__ rb2,
                                               float* __restrict__ out) {
    int cnt = g_cnt;
    int m0 = blockIdx.x * 128;
    if (m0 >= cnt) return;
    int n0 = blockIdx.y * 128;
    float acc[8][8];
    gemm_core<false, false>(g_R1, THD, rw2, HD, THD, m0, n0,
                            nullptr, nullptr, nullptr, nullptr, cnt, acc);
    int ty = threadIdx.x >> 4, tx = threadIdx.x & 15;
#pragma unroll
    for (int i = 0; i < 8; i++) {
        int m = m0 + ty * 8 + i;
        if (m >= cnt) break;
        int token = g_vidx[m];
#pragma unroll
        for (int j = 0; j < 8; j++) {
            int n = n0 + tx * 8 + j;
            out[(size_t)token * HD + n] = acc[i][j] + rb2[n];
        }
    }
}

// ---------------- launch ----------------
extern "C" void kernel_launch(void* const* d_in, const int* in_sizes, int n_in,
                              void* d_out, int out_size) {
    (void)in_sizes; (void)n_in; (void)out_size;
    const float* X   = (const float*)d_in[0];
    const float* tab = (const float*)d_in[1];
    const float* gw  = (const float*)d_in[2];
    const float* gb  = (const float*)d_in[3];
    const float* sw1 = (const float*)d_in[4];
    const float* sb1 = (const float*)d_in[5];
    const float* sw2 = (const float*)d_in[6];
    const float* sb2 = (const float*)d_in[7];
    const float* pw1 = (const float*)d_in[8];
    const float* pb1 = (const float*)d_in[9];
    const float* pw2 = (const float*)d_in[10];
    const float* pb2 = (const float*)d_in[11];
    const float* rw1 = (const float*)d_in[12];
    const float* rb1 = (const float*)d_in[13];
    const float* rw2 = (const float*)d_in[14];
    const float* rb2 = (const float*)d_in[15];
    float* out = (float*)d_out;

    // phase A: precompute (g_scratchA holds W_comb partials)
    k_wcombp<<<dim3(4, 4, 8), 256>>>(pw2, rw1);
    k_wcomb_red<<<(THD * THD + 255) / 256, 256>>>();
    k_embproj<<<TD, 512>>>(tab, pw1);
    k_bcombp<<<16, 512>>>(pb2, rw1);
    k_bcomb_red<<<2, 256>>>();
    k_gatedot<<<2048, 256>>>(X, gw, gb);
    // phase B: selector over all tokens (g_scratchA becomes H1)
    k_pass1sel<<<dim3(128, 4), 256>>>(X, sw1, sb1);
    k_pass2<<<dim3(128, 1), 256>>>(sw2, sb2);
    k_post<<<2048, 256>>>(out);
    // phase C: compacted value path + invalid copy
    k_copyinv<<<MTOK, 512>>>(X, out);
    k_pass1b<<<dim3(128, 8), 256>>>(X, pw1, rw1);
    k_pass4<<<dim3(128, 4), 256>>>(pb1, rb1);
    k_pass5<<<dim3(128, 16), 256>>>(rw2, rb2, out);
}

// round 5
// speedup vs baseline: 2.1649x; 1.3315x over previous
#include <cuda_runtime.h>
#include <math.h>
#include <float.h>

// ToolCallingModule — fused + validity-compacted, tf32 tensor-core value path.
// Shapes (fixed): B=4,S=4096 -> M=16384 tokens; H=2048, E=256, TH=512, T=128, TOPK=3.
// Output layout (float32): [enhanced 16384*2048][tool_probs 16384*128][should_call 16384]
//
// Structure:
//   precompute:  emb_proj (128x512), W_comb (512x512), bias_comb (512)   [fp32]
//   selector:    H1 = relu(X@sel_w1+b); logits = H1@sel_w2+b  (ALL tokens, fp32 —
//                top-k / gate decisions must be bit-faithful vs fp32 reference)
//   compaction:  tokens with any_valid (~44%) -> compact list
//   value path (tf32 mma.sync, decisions already fixed so only values carry error):
//     pass1b: [Xpg|Xri] = X[vidx] @ [pg_w1[:H] | ri_w1[:H]]
//     pass4 : R1 = relu(Xri + relu(Xpg+emb_proj[tool]+pg_b1)@W_comb + bias_comb + ri_b1)
//     pass5 : out[vidx] = R1 @ ri_w2 + ri_b2
//   invalid tokens: out = X (copy)

#define MTOK 16384
#define HD   2048
#define ED   256
#define THD  512
#define TD   128
#define NREG 64

#define OUT_PROBS  (MTOK * HD)
#define OUT_SHOULD (MTOK * HD + MTOK * TD)

// ---------------- scratch (static device globals; no allocation) ----------------
__device__ __align__(16) float g_scratchA[MTOK * THD];  // (A) Wcomb partials, (B) H1
__device__ __align__(16) float g_Xpg[MTOK * THD];   // compact rows [cnt, 512]
__device__ __align__(16) float g_Xri[MTOK * THD];   // compact rows [cnt, 512]
__device__ __align__(16) float g_R1[MTOK * THD];    // compact rows [cnt, 512]
__device__ __align__(16) float g_logits[MTOK * TD];
__device__ __align__(16) float g_Wcomb[THD * THD];
__device__ __align__(16) float g_embproj[TD * THD];
__device__ __align__(16) float g_bcP[16 * THD];
__device__ __align__(16) float g_bcomb[THD];
__device__ float g_gatedot[MTOK];
__device__ int   g_anyv[MTOK];
__device__ int   g_vidx[MTOK];   // compact -> token
__device__ int   g_ctool[MTOK];  // compact -> selected tool id
__device__ int   g_cnt;

// ================= fp32 SIMT GEMM core (selector + precompute) ==================
template <bool TRA, bool GATHER>
__device__ __forceinline__ void gemm_core(
    const float* __restrict__ A, int lda,
    const float* __restrict__ B, int ldb,
    int K, int m0, int n0,
    const float* __restrict__ addTab,
    const int*   __restrict__ rowTool,
    const float* __restrict__ kBias,
    const int*   __restrict__ vidx, int cnt,
    float acc[8][8])
{
    __shared__ float As[16][128];
    __shared__ float Bs[16][128];

    const int t  = threadIdx.x;
    const int ty = t >> 4;
    const int tx = t & 15;
    const int ar = t >> 2;
    const int ac = (t & 3) << 2;
    const int br = t >> 5;
    const int bn = (t & 31) << 2;

    int row0 = m0 + ar, row1 = m0 + ar + 64;
    if (GATHER) {
        row0 = (row0 < cnt) ? vidx[row0] : 0;
        row1 = (row1 < cnt) ? vidx[row1] : 0;
    }
    int tool0 = 0, tool1 = 0;
    if (TRA) {
        tool0 = (m0 + ar      < cnt) ? rowTool[m0 + ar]      : 0;
        tool1 = (m0 + ar + 64 < cnt) ? rowTool[m0 + ar + 64] : 0;
    }

#pragma unroll
    for (int i = 0; i < 8; i++)
#pragma unroll
        for (int j = 0; j < 8; j++) acc[i][j] = 0.0f;

    const float* Arow0 = A + (size_t)row0 * lda;
    const float* Arow1 = A + (size_t)row1 * lda;

    for (int k0 = 0; k0 < K; k0 += 16) {
        float4 a0 = *(const float4*)(Arow0 + k0 + ac);
        float4 a1 = *(const float4*)(Arow1 + k0 + ac);
        if (TRA) {
            float4 e0 = *(const float4*)(addTab + tool0 * THD + k0 + ac);
            float4 e1 = *(const float4*)(addTab + tool1 * THD + k0 + ac);
            float4 bb = *(const float4*)(kBias + k0 + ac);
            a0.x = fmaxf(a0.x + e0.x + bb.x, 0.0f);
            a0.y = fmaxf(a0.y + e0.y + bb.y, 0.0f);
            a0.z = fmaxf(a0.z + e0.z + bb.z, 0.0f);
            a0.w = fmaxf(a0.w + e0.w + bb.w, 0.0f);
            a1.x = fmaxf(a1.x + e1.x + bb.x, 0.0f);
            a1.y = fmaxf(a1.y + e1.y + bb.y, 0.0f);
            a1.z = fmaxf(a1.z + e1.z + bb.z, 0.0f);
            a1.w = fmaxf(a1.w + e1.w + bb.w, 0.0f);
        }
        float4 b0 = *(const float4*)(B + (size_t)(k0 + br) * ldb + n0 + bn);
        float4 b1 = *(const float4*)(B + (size_t)(k0 + br + 8) * ldb + n0 + bn);

        __syncthreads();
        As[ac + 0][ar] = a0.x; As[ac + 1][ar] = a0.y;
        As[ac + 2][ar] = a0.z; As[ac + 3][ar] = a0.w;
        As[ac + 0][ar + 64] = a1.x; As[ac + 1][ar + 64] = a1.y;
        As[ac + 2][ar + 64] = a1.z; As[ac + 3][ar + 64] = a1.w;
        *(float4*)&Bs[br][bn]     = b0;
        *(float4*)&Bs[br + 8][bn] = b1;
        __syncthreads();

#pragma unroll
        for (int kk = 0; kk < 16; kk++) {
            float4 fa0 = *(const float4*)&As[kk][ty * 8];
            float4 fa1 = *(const float4*)&As[kk][ty * 8 + 4];
            float4 fb0 = *(const float4*)&Bs[kk][tx * 8];
            float4 fb1 = *(const float4*)&Bs[kk][tx * 8 + 4];
            float av[8] = {fa0.x, fa0.y, fa0.z, fa0.w, fa1.x, fa1.y, fa1.z, fa1.w};
            float bv[8] = {fb0.x, fb0.y, fb0.z, fb0.w, fb1.x, fb1.y, fb1.z, fb1.w};
#pragma unroll
            for (int i = 0; i < 8; i++)
#pragma unroll
                for (int j = 0; j < 8; j++)
                    acc[i][j] = fmaf(av[i], bv[j], acc[i][j]);
        }
    }
}

// ================= tf32 mma.sync GEMM core (value path) =========================
// 128x128 block, 256 threads = 8 warps as 2(M) x 4(N); warp tile 64x32;
// m16n8k8 tf32 fragments; K-tile 32. A-smem pad 36 -> conflict-free frag loads.

__device__ __forceinline__ unsigned f2tf(float x) {
    unsigned r;
    asm("cvt.rna.tf32.f32 %0, %1;" : "=r"(r) : "f"(x));
    return r;
}

__device__ __forceinline__ void mma_tf32(float c[4], const unsigned a[4], const unsigned b[2]) {
    asm volatile(
        "mma.sync.aligned.m16n8k8.row.col.f32.tf32.tf32.f32 "
        "{%0,%1,%2,%3}, {%4,%5,%6,%7}, {%8,%9}, {%0,%1,%2,%3};"
        : "+f"(c[0]), "+f"(c[1]), "+f"(c[2]), "+f"(c[3])
        : "r"(a[0]), "r"(a[1]), "r"(a[2]), "r"(a[3]), "r"(b[0]), "r"(b[1]));
}

template <bool TRA, bool GATHER>
__device__ __forceinline__ void mma_core(
    const float* __restrict__ A, int lda,
    const float* __restrict__ B, int ldb,
    int K, int m0, int n0,
    const float* __restrict__ addTab,
    const int*   __restrict__ rowTool,
    const float* __restrict__ kBias,
    const int*   __restrict__ vidx, int cnt,
    float acc[4][4][4])
{
    __shared__ float As[128][36];   // [m][k], pad 36 (36%32=4 -> frag lds conflict-free)
    __shared__ float Bs[32][132];   // [k][n], pad 132

    const int t    = threadIdx.x;
    const int warp = t >> 5, lane = t & 31;
    const int wm   = warp >> 2, wn = warp & 3;   // 2 x 4 warp grid
    const int g    = lane >> 2, tg = lane & 3;

    const int lr = t >> 1;            // A load row 0..127
    const int lc = (t & 1) * 16;      // A load col base (0 or 16)
    const int kb = t >> 3;            // B load row 0..31
    const int nb = (t & 7) * 16;      // B load col base

    int arow = m0 + lr;
    if (GATHER) arow = (arow < cnt) ? vidx[arow] : 0;
    int tool0 = 0;
    if (TRA) tool0 = (m0 + lr < cnt) ? rowTool[m0 + lr] : 0;

#pragma unroll
    for (int mi = 0; mi < 4; mi++)
#pragma unroll
        for (int nj = 0; nj < 4; nj++)
#pragma unroll
            for (int q = 0; q < 4; q++) acc[mi][nj][q] = 0.0f;

    const float* Arow = A + (size_t)arow * lda;
    const float* Erow = TRA ? (addTab + tool0 * THD) : (const float*)0;

    for (int k0 = 0; k0 < K; k0 += 32) {
        float4 av[4], bv[4];
#pragma unroll
        for (int i = 0; i < 4; i++) {
            av[i] = *(const float4*)(Arow + k0 + lc + i * 4);
            if (TRA) {
                float4 e  = *(const float4*)(Erow  + k0 + lc + i * 4);
                float4 bb = *(const float4*)(kBias + k0 + lc + i * 4);
                av[i].x = fmaxf(av[i].x + e.x + bb.x, 0.0f);
                av[i].y = fmaxf(av[i].y + e.y + bb.y, 0.0f);
                av[i].z = fmaxf(av[i].z + e.z + bb.z, 0.0f);
                av[i].w = fmaxf(av[i].w + e.w + bb.w, 0.0f);
            }
            bv[i] = *(const float4*)(B + (size_t)(k0 + kb) * ldb + n0 + nb + i * 4);
        }
        __syncthreads();
#pragma unroll
        for (int i = 0; i < 4; i++) {
            float4 ca = make_float4(__uint_as_float(f2tf(av[i].x)),
                                    __uint_as_float(f2tf(av[i].y)),
                                    __uint_as_float(f2tf(av[i].z)),
                                    __uint_as_float(f2tf(av[i].w)));
            *(float4*)&As[lr][lc + i * 4] = ca;
            float4 cb = make_float4(__uint_as_float(f2tf(bv[i].x)),
                                    __uint_as_float(f2tf(bv[i].y)),
                                    __uint_as_float(f2tf(bv[i].z)),
                                    __uint_as_float(f2tf(bv[i].w)));
            *(float4*)&Bs[kb][nb + i * 4] = cb;
        }
        __syncthreads();

#pragma unroll
        for (int ks = 0; ks < 4; ks++) {
            unsigned a[4][4], b[4][2];
#pragma unroll
            for (int mi = 0; mi < 4; mi++) {
                int m = wm * 64 + mi * 16;
                a[mi][0] = __float_as_uint(As[m + g    ][ks * 8 + tg    ]);
                a[mi][1] = __float_as_uint(As[m + g + 8][ks * 8 + tg    ]);
                a[mi][2] = __float_as_uint(As[m + g    ][ks * 8 + tg + 4]);
                a[mi][3] = __float_as_uint(As[m + g + 8][ks * 8 + tg + 4]);
            }
#pragma unroll
            for (int nj = 0; nj < 4; nj++) {
                int n = wn * 32 + nj * 8 + g;
                b[nj][0] = __float_as_uint(Bs[ks * 8 + tg    ][n]);
                b[nj][1] = __float_as_uint(Bs[ks * 8 + tg + 4][n]);
            }
#pragma unroll
            for (int mi = 0; mi < 4; mi++)
#pragma unroll
                for (int nj = 0; nj < 4; nj++)
                    mma_tf32(acc[mi][nj], a[mi], b[nj]);
        }
    }
}

// ---------------- precompute kernels (fp32) ----------------

__global__ __launch_bounds__(256) void k_wcombp(const float* __restrict__ pw2,
                                                const float* __restrict__ rw1) {
    int z = blockIdx.z;
    float acc[8][8];
    gemm_core<false, false>(pw2 + z * 256, HD,
                            rw1 + (size_t)(HD + z * 256) * THD, THD,
                            256, blockIdx.x * 128, blockIdx.y * 128,
                            nullptr, nullptr, nullptr, nullptr, 0, acc);
    int ty = threadIdx.x >> 4, tx = threadIdx.x & 15;
    float* dst = g_scratchA + (size_t)z * THD * THD;
#pragma unroll
    for (int i = 0; i < 8; i++) {
        int m = blockIdx.x * 128 + ty * 8 + i;
#pragma unroll
        for (int j = 0; j < 8; j++)
            dst[m * THD + blockIdx.y * 128 + tx * 8 + j] = acc[i][j];
    }
}

__global__ void k_wcomb_red() {
    int idx = blockIdx.x * blockDim.x + threadIdx.x;
    if (idx >= THD * THD) return;
    float s = 0.0f;
#pragma unroll
    for (int z = 0; z < 8; z++) s += g_scratchA[(size_t)z * THD * THD + idx];
    g_Wcomb[idx] = s;
}

__global__ __launch_bounds__(512) void k_embproj(const float* __restrict__ tab,
                                                 const float* __restrict__ pw1) {
    __shared__ float st[ED];
    int t = blockIdx.x;
    if (threadIdx.x < ED) st[threadIdx.x] = tab[t * ED + threadIdx.x];
    __syncthreads();
    int j = threadIdx.x;
    float acc = 0.0f;
    for (int e = 0; e < ED; e++)
        acc = fmaf(st[e], __ldg(pw1 + (size_t)(HD + e) * THD + j), acc);
    g_embproj[t * THD + j] = acc;
}

__global__ __launch_bounds__(512) void k_bcombp(const float* __restrict__ pb2,
                                                const float* __restrict__ rw1) {
    int z = blockIdx.x;
    int j = threadIdx.x;
    float acc = 0.0f;
    for (int k = z * 128; k < z * 128 + 128; k++)
        acc = fmaf(__ldg(pb2 + k), __ldg(rw1 + (size_t)(HD + k) * THD + j), acc);
    g_bcP[z * THD + j] = acc;
}

__global__ void k_bcomb_red() {
    int j = blockIdx.x * blockDim.x + threadIdx.x;
    if (j >= THD) return;
    float s = 0.0f;
#pragma unroll
    for (int z = 0; z < 16; z++) s += g_bcP[z * THD + j];
    g_bcomb[j] = s;
}

// gate dot: one warp per token; sigmoid(x)>0.5 <=> x>0. Resets compaction counter.
__global__ __launch_bounds__(256) void k_gatedot(const float* __restrict__ X,
                                                 const float* __restrict__ gw,
                                                 const float* __restrict__ gb) {
    if (blockIdx.x == 0 && threadIdx.x == 0) g_cnt = 0;
    int warp = (blockIdx.x * blockDim.x + threadIdx.x) >> 5;
    int lane = threadIdx.x & 31;
    if (warp >= MTOK) return;
    const float* x = X + (size_t)warp * HD;
    float s = 0.0f;
    for (int k = lane; k < HD; k += 32) s = fmaf(x[k], __ldg(gw + k), s);
#pragma unroll
    for (int off = 16; off; off >>= 1) s += __shfl_xor_sync(0xFFFFFFFFu, s, off);
    if (lane == 0) g_gatedot[warp] = s + gb[0];
}

// ---------------- selector path (all tokens, fp32) ----------------

__global__ __launch_bounds__(256) void k_pass1sel(const float* __restrict__ X,
                                                  const float* __restrict__ sw1,
                                                  const float* __restrict__ sb1) {
    int m0  = blockIdx.x * 128;
    int nc0 = blockIdx.y * 128;
    float acc[8][8];
    gemm_core<false, false>(X, HD, sw1, THD, HD, m0, nc0,
                            nullptr, nullptr, nullptr, nullptr, 0, acc);
    int ty = threadIdx.x >> 4, tx = threadIdx.x & 15;
#pragma unroll
    for (int i = 0; i < 8; i++) {
        int m = m0 + ty * 8 + i;
#pragma unroll
        for (int j = 0; j < 8; j++) {
            int n = nc0 + tx * 8 + j;
            g_scratchA[m * THD + n] = fmaxf(acc[i][j] + sb1[n], 0.0f);  // H1
        }
    }
}

__global__ __launch_bounds__(256) void k_pass2(const float* __restrict__ sw2,
                                               const float* __restrict__ sb2) {
    int m0 = blockIdx.x * 128;
    float acc[8][8];
    gemm_core<false, false>(g_scratchA, THD, sw2, TD, THD, m0, 0,
                            nullptr, nullptr, nullptr, nullptr, 0, acc);
    int ty = threadIdx.x >> 4, tx = threadIdx.x & 15;
#pragma unroll
    for (int i = 0; i < 8; i++) {
        int m = m0 + ty * 8 + i;
#pragma unroll
        for (int j = 0; j < 8; j++) {
            int n = tx * 8 + j;
            g_logits[m * TD + n] = acc[i][j] + sb2[n];
        }
    }
}

// post: softmax + top-3 + gate/validity + compaction; one warp per token
__global__ __launch_bounds__(256) void k_post(float* __restrict__ out) {
    int warp = (blockIdx.x * blockDim.x + threadIdx.x) >> 5;
    int lane = threadIdx.x & 31;
    if (warp >= MTOK) return;
    const float* l = g_logits + warp * TD;

    float v[4];
#pragma unroll
    for (int i = 0; i < 4; i++) v[i] = l[lane + 32 * i];

    float mx = fmaxf(fmaxf(v[0], v[1]), fmaxf(v[2], v[3]));
#pragma unroll
    for (int off = 16; off; off >>= 1) mx = fmaxf(mx, __shfl_xor_sync(0xFFFFFFFFu, mx, off));

    float e[4], s = 0.0f;
#pragma unroll
    for (int i = 0; i < 4; i++) { e[i] = expf(v[i] - mx); s += e[i]; }
#pragma unroll
    for (int off = 16; off; off >>= 1) s += __shfl_xor_sync(0xFFFFFFFFu, s, off);
    float inv = 1.0f / s;
#pragma unroll
    for (int i = 0; i < 4; i++)
        out[OUT_PROBS + warp * TD + lane + 32 * i] = e[i] * inv;

    int chosen[3];
    unsigned excl = 0;
#pragma unroll
    for (int p = 0; p < 3; p++) {
        float bv = -FLT_MAX;
        int bi = 1 << 30;
#pragma unroll
        for (int i = 0; i < 4; i++) {
            if (!((excl >> i) & 1u)) {
                int idx = lane + 32 * i;
                if (v[i] > bv) { bv = v[i]; bi = idx; }
            }
        }
#pragma unroll
        for (int off = 16; off; off >>= 1) {
            float ov = __shfl_xor_sync(0xFFFFFFFFu, bv, off);
            int   oi = __shfl_xor_sync(0xFFFFFFFFu, bi, off);
            if (ov > bv || (ov == bv && oi < bi)) { bv = ov; bi = oi; }
        }
        chosen[p] = bi;
        if ((bi & 31) == lane) excl |= 1u << (bi >> 5);
    }

    bool should = g_gatedot[warp] > 0.0f;
    int last = -1;
#pragma unroll
    for (int k = 0; k < 3; k++)
        if (chosen[k] < NREG && should) last = k;
    int selk = last < 0 ? 0 : last;

    if (lane == 0) {
        int anyv = (last >= 0) ? 1 : 0;
        g_anyv[warp] = anyv;
        out[OUT_SHOULD + warp] = should ? 1.0f : 0.0f;
        if (anyv) {
            int pos = atomicAdd(&g_cnt, 1);
            g_vidx[pos]  = warp;
            g_ctool[pos] = chosen[selk];
        }
    }
}

// invalid tokens: out row = X row
__global__ __launch_bounds__(512) void k_copyinv(const float* __restrict__ X,
                                                 float* __restrict__ out) {
    int token = blockIdx.x;
    if (g_anyv[token]) return;
    const float4* src = (const float4*)(X + (size_t)token * HD);
    float4* dst = (float4*)(out + (size_t)token * HD);
    dst[threadIdx.x] = src[threadIdx.x];
}

// ---------------- compacted value path (tf32 mma) ----------------

// [Xpg | Xri](compact) = X[vidx] @ [pg_w1[:H] | ri_w1[:H]]
__global__ __launch_bounds__(256) void k_pass1b_mma(const float* __restrict__ X,
                                                    const float* __restrict__ pw1,
                                                    const float* __restrict__ rw1) {
    int cnt = g_cnt;
    int m0 = blockIdx.x * 128;
    if (m0 >= cnt) return;
    int grp = blockIdx.y >> 2;          // 0=pg, 1=ri
    int nc0 = (blockIdx.y & 3) * 128;
    const float* B = grp ? rw1 : pw1;
    float acc[4][4][4];
    mma_core<false, true>(X, HD, B, THD, HD, m0, nc0,
                          nullptr, nullptr, nullptr, g_vidx, cnt, acc);
    float* dst = grp ? g_Xri : g_Xpg;
    int warp = threadIdx.x >> 5, lane = threadIdx.x & 31;
    int wm = warp >> 2, wn = warp & 3, g = lane >> 2, tg = lane & 3;
#pragma unroll
    for (int mi = 0; mi < 4; mi++) {
        int r0 = m0 + wm * 64 + mi * 16 + g;
        int r1 = r0 + 8;
#pragma unroll
        for (int nj = 0; nj < 4; nj++) {
            int c = nc0 + wn * 32 + nj * 8 + tg * 2;
            if (r0 < cnt) *(float2*)&dst[r0 * THD + c] = make_float2(acc[mi][nj][0], acc[mi][nj][1]);
            if (r1 < cnt) *(float2*)&dst[r1 * THD + c] = make_float2(acc[mi][nj][2], acc[mi][nj][3]);
        }
    }
}

// R1 = relu(Xri + relu(Xpg + embproj[tool] + pg_b1) @ Wcomb + bcomb + ri_b1)
__global__ __launch_bounds__(256) void k_pass4_mma(const float* __restrict__ pb1,
                                                   const float* __restrict__ rb1) {
    int cnt = g_cnt;
    int m0 = blockIdx.x * 128;
    if (m0 >= cnt) return;
    int n0 = blockIdx.y * 128;
    float acc[4][4][4];
    mma_core<true, false>(g_Xpg, THD, g_Wcomb, THD, THD, m0, n0,
                          g_embproj, g_ctool, pb1, nullptr, cnt, acc);
    int warp = threadIdx.x >> 5, lane = threadIdx.x & 31;
    int wm = warp >> 2, wn = warp & 3, g = lane >> 2, tg = lane & 3;
#pragma unroll
    for (int mi = 0; mi < 4; mi++) {
        int r0 = m0 + wm * 64 + mi * 16 + g;
        int r1 = r0 + 8;
#pragma unroll
        for (int nj = 0; nj < 4; nj++) {
            int c = n0 + wn * 32 + nj * 8 + tg * 2;
            float ca0 = g_bcomb[c] + rb1[c];
            float ca1 = g_bcomb[c + 1] + rb1[c + 1];
            if (r0 < cnt) {
                float2 x = *(const float2*)&g_Xri[r0 * THD + c];
                *(float2*)&g_R1[r0 * THD + c] =
                    make_float2(fmaxf(acc[mi][nj][0] + x.x + ca0, 0.0f),
                                fmaxf(acc[mi][nj][1] + x.y + ca1, 0.0f));
            }
            if (r1 < cnt) {
                float2 x = *(const float2*)&g_Xri[r1 * THD + c];
                *(float2*)&g_R1[r1 * THD + c] =
                    make_float2(fmaxf(acc[mi][nj][2] + x.x + ca0, 0.0f),
                                fmaxf(acc[mi][nj][3] + x.y + ca1, 0.0f));
            }
        }
    }
}

// out[vidx] = R1 @ ri_w2 + ri_b2
__global__ __launch_bounds__(256) void k_pass5_mma(const float* __restrict__ rw2,
                                                   const float* __restrict__ rb2,
                                                   float* __restrict__ out) {
    int cnt = g_cnt;
    int m0 = blockIdx.x * 128;
    if (m0 >= cnt) return;
    int n0 = blockIdx.y * 128;
    float acc[4][4][4];
    mma_core<false, false>(g_R1, THD, rw2, HD, THD, m0, n0,
                           nullptr, nullptr, nullptr, nullptr, cnt, acc);
    int warp = threadIdx.x >> 5, lane = threadIdx.x & 31;
    int wm = warp >> 2, wn = warp & 3, g = lane >> 2, tg = lane & 3;
#pragma unroll
    for (int mi = 0; mi < 4; mi++) {
        int r0 = m0 + wm * 64 + mi * 16 + g;
        int r1 = r0 + 8;
#pragma unroll
        for (int nj = 0; nj < 4; nj++) {
            int c = n0 + wn * 32 + nj * 8 + tg * 2;
            float b0 = rb2[c], b1 = rb2[c + 1];
            if (r0 < cnt) {
                int tok = g_vidx[r0];
                *(float2*)&out[(size_t)tok * HD + c] =
                    make_float2(acc[mi][nj][0] + b0, acc[mi][nj][1] + b1);
            }
            if (r1 < cnt) {
                int tok = g_vidx[r1];
                *(float2*)&out[(size_t)tok * HD + c] =
                    make_float2(acc[mi][nj][2] + b0, acc[mi][nj][3] + b1);
            }
        }
    }
}

// ---------------- launch ----------------
extern "C" void kernel_launch(void* const* d_in, const int* in_sizes, int n_in,
                              void* d_out, int out_size) {
    (void)in_sizes; (void)n_in; (void)out_size;
    const float* X   = (const float*)d_in[0];
    const float* tab = (const float*)d_in[1];
    const float* gw  = (const float*)d_in[2];
    const float* gb  = (const float*)d_in[3];
    const float* sw1 = (const float*)d_in[4];
    const float* sb1 = (const float*)d_in[5];
    const float* sw2 = (const float*)d_in[6];
    const float* sb2 = (const float*)d_in[7];
    const float* pw1 = (const float*)d_in[8];
    const float* pb1 = (const float*)d_in[9];
    const float* pw2 = (const float*)d_in[10];
    const float* pb2 = (const float*)d_in[11];
    const float* rw1 = (const float*)d_in[12];
    const float* rb1 = (const float*)d_in[13];
    const float* rw2 = (const float*)d_in[14];
    const float* rb2 = (const float*)d_in[15];
    float* out = (float*)d_out;

    // phase A: precompute (g_scratchA holds W_comb partials)
    k_wcombp<<<dim3(4, 4, 8), 256>>>(pw2, rw1);
    k_wcomb_red<<<(THD * THD + 255) / 256, 256>>>();
    k_embproj<<<TD, 512>>>(tab, pw1);
    k_bcombp<<<16, 512>>>(pb2, rw1);
    k_bcomb_red<<<2, 256>>>();
    k_gatedot<<<2048, 256>>>(X, gw, gb);
    // phase B: selector over all tokens (fp32; g_scratchA becomes H1)
    k_pass1sel<<<dim3(128, 4), 256>>>(X, sw1, sb1);
    k_pass2<<<dim3(128, 1), 256>>>(sw2, sb2);
    k_post<<<2048, 256>>>(out);
    // phase C: compacted value path (tf32 mma) + invalid copy
    k_copyinv<<<MTOK, 512>>>(X, out);
    k_pass1b_mma<<<dim3(128, 8), 256>>>(X, pw1, rw1);
    k_pass4_mma<<<dim3(128, 4), 256>>>(pb1, rb1);
    k_pass5_mma<<<dim3(128, 16), 256>>>(rw2, rb2, out);
}